// round 12
// baseline (speedup 1.0000x reference)
#include <cuda_runtime.h>
#include <math.h>

#define NN 1024
#define DD 64
#define MIN_NORM 1e-15f
#define PROJ_EPS 4e-3f
#define MAXDEG 48
#define PT 17             // partial row stride in float4s (conflict-free)
#define TPR 128

__device__ __forceinline__ float artanh_fast(float z) {
    z = fminf(z, 1.0f - 1e-7f);
    z = fmaxf(z, -1.0f + 1e-7f);
    return 0.5f * __logf(__fdividef(1.0f + z, 1.0f - z));
}

// saturating fast tanh: clamp arg so __expf never overflows (tanh(10)=1-4e-9)
__device__ __forceinline__ float tanh_fast(float t) {
    t = fminf(t, 10.0f);              // t >= 0 at our call site
    float e2 = __expf(2.0f * t);
    return __fdividef(e2 - 1.0f, e2 + 1.0f);
}

__global__ void __launch_bounds__(TPR) hyp_all(
        const float* __restrict__ x,
        const float* __restrict__ adj,
        const float* __restrict__ W,
        const float* __restrict__ b,
        float* __restrict__ out) {
    __shared__ float4 sh_p4[DD / 4];
    __shared__ float4 sh_wr4[DD / 4];
    __shared__ int    sh_j[MAXDEG];
    __shared__ float  sh_a[MAXDEG];           // adj value, then alpha
    __shared__ float  sh_bA[MAXDEG];          // alpha * A  (for beta)
    __shared__ float  sm_q[MAXDEG * DD];      // staged neighbor rows
    __shared__ float4 sh_pt[MAXDEG * PT];     // packed partials (dp,y2,qw,0)
    __shared__ float  sh_acc[8 * DD];
    __shared__ float  sh_red[8];
    __shared__ int    sh_wcnt[4];

    int tid  = threadIdx.x;
    int lane = tid & 31;
    int wid  = tid >> 5;
    int i    = blockIdx.x;

    // ---- adj row prefetch first: 2 independent float4 per thread ----
    const float4* arow = (const float4*)(adj + (size_t)i * NN);
    float4 a0 = arow[tid];
    float4 a1 = arow[tid + TPR];

    // own-row point + W into shared (overlaps adj loads in flight)
    float pd = 0.0f, wl = 0.0f;
    if (tid < DD) {
        pd = x[i * DD + tid];
        ((float*)sh_p4)[tid]  = pd;
        wl = W[tid];
        ((float*)sh_wr4)[tid] = W[DD + tid];
    }
    float ra = pd * pd, rb = pd * wl;
#pragma unroll
    for (int o = 16; o > 0; o >>= 1) {
        ra += __shfl_xor_sync(0xffffffffu, ra, o);
        rb += __shfl_xor_sync(0xffffffffu, rb, o);
    }
    if (lane == 0) { sh_red[wid * 2] = ra; sh_red[wid * 2 + 1] = rb; }

    // ---- compaction mask + warp scan (register-only, before sync) ----
    unsigned m = 0u;
    if (a0.x != 0.0f) m |= 1u;  if (a0.y != 0.0f) m |= 2u;
    if (a0.z != 0.0f) m |= 4u;  if (a0.w != 0.0f) m |= 8u;
    if (a1.x != 0.0f) m |= 16u; if (a1.y != 0.0f) m |= 32u;
    if (a1.z != 0.0f) m |= 64u; if (a1.w != 0.0f) m |= 128u;
    int nl = __popc(m);
    int v = nl;
#pragma unroll
    for (int o = 1; o < 32; o <<= 1) {
        int u = __shfl_up_sync(0xffffffffu, v, o);
        if (lane >= o) v += u;
    }
    if (lane == 31) sh_wcnt[wid] = v;
    __syncthreads();                                   // sync 1

    float x2i = sh_red[0] + sh_red[2] + sh_red[4] + sh_red[6];
    float spw = sh_red[1] + sh_red[3] + sh_red[5] + sh_red[7];
    float pn  = fmaxf(sqrtf(x2i), MIN_NORM);
    float lefti = __fdividef(artanh_fast(pn), pn) * spw + b[0];
    float B = 1.0f - x2i;
    float two_over_lam = fmaxf(B, MIN_NORM);

    int base = 0;
#pragma unroll
    for (int ww = 0; ww < 4; ww++) if (ww < wid) base += sh_wcnt[ww];
    int cnt = sh_wcnt[0] + sh_wcnt[1] + sh_wcnt[2] + sh_wcnt[3];
    if (cnt > MAXDEG) cnt = MAXDEG;
    int pos = base + v - nl;
    {
        const float* v0 = (const float*)&a0;
        const float* v1 = (const float*)&a1;
#pragma unroll
        for (int c = 0; c < 4; c++) {
            if ((m >> c) & 1u) {
                if (pos < MAXDEG) { sh_j[pos] = tid * 4 + c; sh_a[pos] = v0[c]; }
                pos++;
            }
        }
#pragma unroll
        for (int c = 0; c < 4; c++) {
            if ((m >> (4 + c)) & 1u) {
                if (pos < MAXDEG) { sh_j[pos] = (tid + TPR) * 4 + c; sh_a[pos] = v1[c]; }
                pos++;
            }
        }
    }
    __syncthreads();                                   // sync 2 (sh_j ready)

    // ---- staging + packed partials; batch 1 covers cnt <= 24 ----
    {
        int sub = tid >> 4;            // 0..7: row within pass
        int c4  = tid & 15;            // dim quad
        float4 pq = sh_p4[c4];
        float4 wq = sh_wr4[c4];
        float4 qv[3];
#pragma unroll
        for (int s = 0; s < 3; s++) {
            int r = sub + s * 8;
            if (r < cnt) qv[s] = *(const float4*)(x + (size_t)sh_j[r] * DD + c4 * 4);
        }
#pragma unroll
        for (int s = 0; s < 3; s++) {
            int r = sub + s * 8;
            if (r < cnt) {
                float4 q = qv[s];
                *(float4*)&sm_q[r * DD + c4 * 4] = q;
                float dp = q.x * pq.x + q.y * pq.y + q.z * pq.z + q.w * pq.w;
                float y2 = q.x * q.x  + q.y * q.y  + q.z * q.z  + q.w * q.w;
                float qw = q.x * wq.x + q.y * wq.y + q.z * wq.z + q.w * wq.w;
                sh_pt[r * PT + c4] = make_float4(dp, y2, qw, 0.0f);
            }
        }
        if (cnt > 24) {    // block-uniform branch: rare tail (deg > 24)
#pragma unroll
            for (int s = 3; s < 6; s++) {
                int r = sub + s * 8;
                if (r < cnt) qv[s - 3] = *(const float4*)(x + (size_t)sh_j[r] * DD + c4 * 4);
            }
#pragma unroll
            for (int s = 3; s < 6; s++) {
                int r = sub + s * 8;
                if (r < cnt) {
                    float4 q = qv[s - 3];
                    *(float4*)&sm_q[r * DD + c4 * 4] = q;
                    float dp = q.x * pq.x + q.y * pq.y + q.z * pq.z + q.w * pq.w;
                    float y2 = q.x * q.x  + q.y * q.y  + q.z * q.z  + q.w * q.w;
                    float qw = q.x * wq.x + q.y * wq.y + q.z * wq.z + q.w * wq.w;
                    sh_pt[r * PT + c4] = make_float4(dp, y2, qw, 0.0f);
                }
            }
        }
    }
    __syncthreads();                                   // sync 3

    // ---- phase A: one thread per neighbor, LDS.128 partials + scalar ----
    if (tid < MAXDEG) {
        float alpha = 0.0f, bA = 0.0f;
        if (tid < cnt) {
            float d = 0.0f, y2j = 0.0f, qw = 0.0f;
#pragma unroll
            for (int t = 0; t < 16; t++) {
                float4 pv = sh_pt[tid * PT + t];
                d += pv.x; y2j += pv.y; qw += pv.z;
            }
            float pnj = fmaxf(sqrtf(y2j), MIN_NORM);
            float rightj = __fdividef(artanh_fast(pnj), pnj) * qw;

            float A   = 1.0f - 2.0f * d + y2j;
            float den = 1.0f - 2.0f * d + x2i * y2j;
            float inv_den = __fdividef(1.0f, fmaxf(den, MIN_NORM));
            float num2 = fmaxf(A * A * x2i - 2.0f * A * B * d + B * B * y2j, 0.0f);
            float sn = fmaxf(sqrtf(num2) * inv_den, MIN_NORM);
            float coef = two_over_lam * __fdividef(artanh_fast(sn), sn);
            float wgt  = __fdividef(sh_a[tid], 1.0f + __expf(-(lefti + rightj)));
            alpha = wgt * coef * inv_den;
            bA = alpha * A;
        }
        sh_a[tid]  = alpha;
        sh_bA[tid] = bA;
    }
    __syncthreads();                                   // sync 4 (alphas ready)

    // ---- phase B: 8-way neighbor split x 16 dim quads, LDS.128 ----
    {
        int s  = tid >> 4;
        int c4 = tid & 15;
        float4 acc4 = make_float4(0.0f, 0.0f, 0.0f, 0.0f);
        for (int k = s; k < cnt; k += 8) {
            float al = sh_a[k];
            float4 q = *(const float4*)&sm_q[k * DD + c4 * 4];
            acc4.x = fmaf(al, q.x, acc4.x);
            acc4.y = fmaf(al, q.y, acc4.y);
            acc4.z = fmaf(al, q.z, acc4.z);
            acc4.w = fmaf(al, q.w, acc4.w);
        }
        *(float4*)&sh_acc[s * DD + c4 * 4] = acc4;
    }
    __syncthreads();                                   // sync 5 (last sync)

    // ---- warp-0 epilogue: combine, beta, reductions, scalar math, store ----
    if (wid == 0) {
        // beta = sum alpha*A  (MAXDEG = 48 slots; zeros beyond cnt)
        float beta = sh_bA[lane] + ((lane < MAXDEG - 32) ? sh_bA[lane + 32] : 0.0f);
#pragma unroll
        for (int o = 16; o > 0; o >>= 1)
            beta += __shfl_xor_sync(0xffffffffu, beta, o);

        // combine 8 partials for dims lane and lane+32
        float acc_lo = 0.0f, acc_hi = 0.0f;
#pragma unroll
        for (int s = 0; s < 8; s++) {
            acc_lo += sh_acc[s * DD + lane];
            acc_hi += sh_acc[s * DD + lane + 32];
        }
        float p_lo = ((float*)sh_p4)[lane];
        float p_hi = ((float*)sh_p4)[lane + 32];
        acc_lo = B * acc_lo - beta * p_lo;             // support_t
        acc_hi = B * acc_hi - beta * p_hi;

        // dual reduce: s2 = |support|^2, ap = support . p
        float ea = acc_lo * acc_lo + acc_hi * acc_hi;
        float eb = acc_lo * p_lo  + acc_hi * p_hi;
#pragma unroll
        for (int o = 16; o > 0; o >>= 1) {
            ea += __shfl_xor_sync(0xffffffffu, ea, o);
            eb += __shfl_xor_sync(0xffffffffu, eb, o);
        }
        float s2 = ea, ap = eb;

        // reference epilogue: _expmap(u=x_i, p=support), mobius_add, proj
        float un  = fmaxf(sqrtf(x2i), MIN_NORM);       // |u| = |x_i|
        float tol = fmaxf(1.0f - s2, MIN_NORM);
        float sc  = __fdividef(tanh_fast(__fdividef(un, tol)), un);
        float y2  = sc * sc * x2i;                     // |second|^2
        float xy  = sc * ap;                           // support . second

        float numc = 1.0f + 2.0f * xy + y2;
        float den  = fmaxf(1.0f + 2.0f * xy + s2 * y2, MIN_NORM);
        float inv_den = __fdividef(1.0f, den);
        float c_acc = numc * inv_den;
        float c_p   = (1.0f - s2) * sc * inv_den;

        float r2 = c_acc * c_acc * s2 + 2.0f * c_acc * c_p * ap + c_p * c_p * x2i;
        float n = fmaxf(sqrtf(r2), MIN_NORM);
        float maxnorm = 1.0f - PROJ_EPS;
        float scale = (n > maxnorm) ? __fdividef(maxnorm, n) : 1.0f;

        out[i * DD + lane]      = (c_acc * acc_lo + c_p * p_lo) * scale;
        out[i * DD + lane + 32] = (c_acc * acc_hi + c_p * p_hi) * scale;
    }
}

extern "C" void kernel_launch(void* const* d_in, const int* in_sizes, int n_in,
                              void* d_out, int out_size) {
    const float* x = nullptr; const float* adj = nullptr;
    const float* att_W = nullptr; const float* att_b = nullptr;
    for (int k = 0; k < n_in; k++) {
        int sz = in_sizes[k];
        if (sz == NN * NN)      adj   = (const float*)d_in[k];
        else if (sz == NN * DD) x     = (const float*)d_in[k];
        else if (sz == 2 * DD)  att_W = (const float*)d_in[k];
        else if (sz == 1)       att_b = (const float*)d_in[k];
    }
    float* out = (float*)d_out;

    hyp_all<<<NN, TPR>>>(x, adj, att_W, att_b, out);
}

// round 14
// speedup vs baseline: 1.0295x; 1.0295x over previous
#include <cuda_runtime.h>
#include <math.h>

#define NN 1024
#define DD 64
#define MIN_NORM 1e-15f
#define PROJ_EPS 4e-3f
#define MAXDEG 48
#define TPR 128

__device__ __forceinline__ float artanh_fast(float z) {
    z = fminf(z, 1.0f - 1e-7f);
    z = fmaxf(z, -1.0f + 1e-7f);
    return 0.5f * __logf(__fdividef(1.0f + z, 1.0f - z));
}

// saturating fast tanh: clamp arg so __expf never overflows (tanh(10)=1-4e-9)
__device__ __forceinline__ float tanh_fast(float t) {
    t = fminf(t, 10.0f);              // t >= 0 at our call site
    float e2 = __expf(2.0f * t);
    return __fdividef(e2 - 1.0f, e2 + 1.0f);
}

__global__ void __launch_bounds__(TPR) hyp_all(
        const float* __restrict__ x,
        const float* __restrict__ adj,
        const float* __restrict__ W,
        const float* __restrict__ b,
        float* __restrict__ out) {
    __shared__ float4 sh_p4[DD / 4];
    __shared__ float4 sh_wr4[DD / 4];
    __shared__ int    sh_j[MAXDEG];
    __shared__ float  sh_a[MAXDEG];      // adj value, then alpha
    __shared__ float  sh_bA[MAXDEG];     // alpha * A (for beta)
    __shared__ float4 sh_dyq[MAXDEG];    // per-row (d, |q|^2, q.Wr, 0)
    __shared__ float  sh_acc[8 * DD];
    __shared__ float  sh_red[8];
    __shared__ int    sh_wcnt[4];

    int tid  = threadIdx.x;
    int lane = tid & 31;
    int wid  = tid >> 5;
    int i    = blockIdx.x;

    // ---- adj row prefetch first: 2 independent float4 per thread ----
    const float4* arow = (const float4*)(adj + (size_t)i * NN);
    float4 a0 = arow[tid];
    float4 a1 = arow[tid + TPR];

    // own-row point + W into shared (overlaps adj loads in flight)
    float pd = 0.0f, wl = 0.0f;
    if (tid < DD) {
        pd = x[i * DD + tid];
        ((float*)sh_p4)[tid]  = pd;
        wl = W[tid];
        ((float*)sh_wr4)[tid] = W[DD + tid];
    }
    float ra = pd * pd, rb = pd * wl;
#pragma unroll
    for (int o = 16; o > 0; o >>= 1) {
        ra += __shfl_xor_sync(0xffffffffu, ra, o);
        rb += __shfl_xor_sync(0xffffffffu, rb, o);
    }
    if (lane == 0) { sh_red[wid * 2] = ra; sh_red[wid * 2 + 1] = rb; }

    // ---- compaction mask + warp scan (register-only, before sync) ----
    unsigned m = 0u;
    if (a0.x != 0.0f) m |= 1u;  if (a0.y != 0.0f) m |= 2u;
    if (a0.z != 0.0f) m |= 4u;  if (a0.w != 0.0f) m |= 8u;
    if (a1.x != 0.0f) m |= 16u; if (a1.y != 0.0f) m |= 32u;
    if (a1.z != 0.0f) m |= 64u; if (a1.w != 0.0f) m |= 128u;
    int nl = __popc(m);
    int v = nl;
#pragma unroll
    for (int o = 1; o < 32; o <<= 1) {
        int u = __shfl_up_sync(0xffffffffu, v, o);
        if (lane >= o) v += u;
    }
    if (lane == 31) sh_wcnt[wid] = v;
    __syncthreads();                                   // sync 1

    float x2i = sh_red[0] + sh_red[2] + sh_red[4] + sh_red[6];
    float spw = sh_red[1] + sh_red[3] + sh_red[5] + sh_red[7];
    float pn  = fmaxf(sqrtf(x2i), MIN_NORM);
    float lefti = __fdividef(artanh_fast(pn), pn) * spw + b[0];
    float B = 1.0f - x2i;
    float two_over_lam = fmaxf(B, MIN_NORM);

    int base = 0;
#pragma unroll
    for (int ww = 0; ww < 4; ww++) if (ww < wid) base += sh_wcnt[ww];
    int cnt = sh_wcnt[0] + sh_wcnt[1] + sh_wcnt[2] + sh_wcnt[3];
    if (cnt > MAXDEG) cnt = MAXDEG;
    int pos = base + v - nl;
    {
        const float* v0 = (const float*)&a0;
        const float* v1 = (const float*)&a1;
#pragma unroll
        for (int c = 0; c < 4; c++) {
            if ((m >> c) & 1u) {
                if (pos < MAXDEG) { sh_j[pos] = tid * 4 + c; sh_a[pos] = v0[c]; }
                pos++;
            }
        }
#pragma unroll
        for (int c = 0; c < 4; c++) {
            if ((m >> (4 + c)) & 1u) {
                if (pos < MAXDEG) { sh_j[pos] = (tid + TPR) * 4 + c; sh_a[pos] = v1[c]; }
                pos++;
            }
        }
    }
    __syncthreads();                                   // sync 2 (sh_j ready)

    // ---- staging in REGISTERS + 16-lane butterfly partial reduce ----
    int sub = tid >> 4;                // 0..7: row subgroup
    int c4  = tid & 15;                // dim quad
    bool tail = (cnt > 24);            // block-uniform
    float4 qv[3], qv2[3];
    {
        float4 pq = sh_p4[c4];
        float4 wq = sh_wr4[c4];
#pragma unroll
        for (int s = 0; s < 3; s++) {
            int r = sub + s * 8;
            if (r < cnt) qv[s] = *(const float4*)(x + (size_t)sh_j[r] * DD + c4 * 4);
        }
        if (tail) {
#pragma unroll
            for (int s = 3; s < 6; s++) {
                int r = sub + s * 8;
                if (r < cnt) qv2[s - 3] = *(const float4*)(x + (size_t)sh_j[r] * DD + c4 * 4);
            }
        }
#pragma unroll
        for (int s = 0; s < 3; s++) {
            int r = sub + s * 8;       // uniform within the 16-lane group
            float dp = 0.0f, y2 = 0.0f, qw = 0.0f;
            if (r < cnt) {
                float4 q = qv[s];
                dp = q.x * pq.x + q.y * pq.y + q.z * pq.z + q.w * pq.w;
                y2 = q.x * q.x  + q.y * q.y  + q.z * q.z  + q.w * q.w;
                qw = q.x * wq.x + q.y * wq.y + q.z * wq.z + q.w * wq.w;
            }
#pragma unroll
            for (int o = 1; o < 16; o <<= 1) {   // stays within 16-lane half
                dp += __shfl_xor_sync(0xffffffffu, dp, o);
                y2 += __shfl_xor_sync(0xffffffffu, y2, o);
                qw += __shfl_xor_sync(0xffffffffu, qw, o);
            }
            if (r < cnt && c4 == 0) sh_dyq[r] = make_float4(dp, y2, qw, 0.0f);
        }
        if (tail) {
#pragma unroll
            for (int s = 3; s < 6; s++) {
                int r = sub + s * 8;
                float dp = 0.0f, y2 = 0.0f, qw = 0.0f;
                if (r < cnt) {
                    float4 q = qv2[s - 3];
                    dp = q.x * pq.x + q.y * pq.y + q.z * pq.z + q.w * pq.w;
                    y2 = q.x * q.x  + q.y * q.y  + q.z * q.z  + q.w * q.w;
                    qw = q.x * wq.x + q.y * wq.y + q.z * wq.z + q.w * wq.w;
                }
#pragma unroll
                for (int o = 1; o < 16; o <<= 1) {
                    dp += __shfl_xor_sync(0xffffffffu, dp, o);
                    y2 += __shfl_xor_sync(0xffffffffu, y2, o);
                    qw += __shfl_xor_sync(0xffffffffu, qw, o);
                }
                if (r < cnt && c4 == 0) sh_dyq[r] = make_float4(dp, y2, qw, 0.0f);
            }
        }
    }
    __syncthreads();                                   // sync 3 (dyq ready)

    // ---- phase A: one thread per neighbor, one LDS.128 + scalar chain ----
    if (tid < MAXDEG) {
        float alpha = 0.0f, bA = 0.0f;
        if (tid < cnt) {
            float4 dyq = sh_dyq[tid];
            float d = dyq.x, y2j = dyq.y, qw = dyq.z;

            float pnj = fmaxf(sqrtf(y2j), MIN_NORM);
            float rightj = __fdividef(artanh_fast(pnj), pnj) * qw;

            float A   = 1.0f - 2.0f * d + y2j;
            float den = 1.0f - 2.0f * d + x2i * y2j;
            float inv_den = __fdividef(1.0f, fmaxf(den, MIN_NORM));
            float num2 = fmaxf(A * A * x2i - 2.0f * A * B * d + B * B * y2j, 0.0f);
            float sn = fmaxf(sqrtf(num2) * inv_den, MIN_NORM);
            float coef = two_over_lam * __fdividef(artanh_fast(sn), sn);
            float wgt  = __fdividef(sh_a[tid], 1.0f + __expf(-(lefti + rightj)));
            alpha = wgt * coef * inv_den;
            bA = alpha * A;
        }
        sh_a[tid]  = alpha;
        sh_bA[tid] = bA;
    }
    __syncthreads();                                   // sync 4 (alphas ready)

    // ---- phase B: register-resident q, alpha via LDS broadcast ----
    {
        float4 acc4 = make_float4(0.0f, 0.0f, 0.0f, 0.0f);
#pragma unroll
        for (int s = 0; s < 3; s++) {
            int r = sub + s * 8;
            if (r < cnt) {
                float al = sh_a[r];
                acc4.x = fmaf(al, qv[s].x, acc4.x);
                acc4.y = fmaf(al, qv[s].y, acc4.y);
                acc4.z = fmaf(al, qv[s].z, acc4.z);
                acc4.w = fmaf(al, qv[s].w, acc4.w);
            }
        }
        if (tail) {
#pragma unroll
            for (int s = 3; s < 6; s++) {
                int r = sub + s * 8;
                if (r < cnt) {
                    float al = sh_a[r];
                    acc4.x = fmaf(al, qv2[s - 3].x, acc4.x);
                    acc4.y = fmaf(al, qv2[s - 3].y, acc4.y);
                    acc4.z = fmaf(al, qv2[s - 3].z, acc4.z);
                    acc4.w = fmaf(al, qv2[s - 3].w, acc4.w);
                }
            }
        }
        *(float4*)&sh_acc[sub * DD + c4 * 4] = acc4;
    }
    __syncthreads();                                   // sync 5 (last sync)

    // ---- warp-0 epilogue: combine, beta, reductions, scalar math, store ----
    if (wid == 0) {
        // beta = sum alpha*A  (MAXDEG = 48 slots; zeros beyond cnt)
        float beta = sh_bA[lane] + ((lane < MAXDEG - 32) ? sh_bA[lane + 32] : 0.0f);
#pragma unroll
        for (int o = 16; o > 0; o >>= 1)
            beta += __shfl_xor_sync(0xffffffffu, beta, o);

        // combine 8 partials for dims lane and lane+32
        float acc_lo = 0.0f, acc_hi = 0.0f;
#pragma unroll
        for (int s = 0; s < 8; s++) {
            acc_lo += sh_acc[s * DD + lane];
            acc_hi += sh_acc[s * DD + lane + 32];
        }
        float p_lo = ((float*)sh_p4)[lane];
        float p_hi = ((float*)sh_p4)[lane + 32];
        acc_lo = B * acc_lo - beta * p_lo;             // support_t
        acc_hi = B * acc_hi - beta * p_hi;

        // dual reduce: s2 = |support|^2, ap = support . p
        float ea = acc_lo * acc_lo + acc_hi * acc_hi;
        float eb = acc_lo * p_lo  + acc_hi * p_hi;
#pragma unroll
        for (int o = 16; o > 0; o >>= 1) {
            ea += __shfl_xor_sync(0xffffffffu, ea, o);
            eb += __shfl_xor_sync(0xffffffffu, eb, o);
        }
        float s2 = ea, ap = eb;

        // reference epilogue: _expmap(u=x_i, p=support), mobius_add, proj
        float un  = fmaxf(sqrtf(x2i), MIN_NORM);       // |u| = |x_i|
        float tol = fmaxf(1.0f - s2, MIN_NORM);
        float sc  = __fdividef(tanh_fast(__fdividef(un, tol)), un);
        float y2  = sc * sc * x2i;                     // |second|^2
        float xy  = sc * ap;                           // support . second

        float numc = 1.0f + 2.0f * xy + y2;
        float den  = fmaxf(1.0f + 2.0f * xy + s2 * y2, MIN_NORM);
        float inv_den = __fdividef(1.0f, den);
        float c_acc = numc * inv_den;
        float c_p   = (1.0f - s2) * sc * inv_den;

        float r2 = c_acc * c_acc * s2 + 2.0f * c_acc * c_p * ap + c_p * c_p * x2i;
        float n = fmaxf(sqrtf(r2), MIN_NORM);
        float maxnorm = 1.0f - PROJ_EPS;
        float scale = (n > maxnorm) ? __fdividef(maxnorm, n) : 1.0f;

        out[i * DD + lane]      = (c_acc * acc_lo + c_p * p_lo) * scale;
        out[i * DD + lane + 32] = (c_acc * acc_hi + c_p * p_hi) * scale;
    }
}

extern "C" void kernel_launch(void* const* d_in, const int* in_sizes, int n_in,
                              void* d_out, int out_size) {
    const float* x = nullptr; const float* adj = nullptr;
    const float* att_W = nullptr; const float* att_b = nullptr;
    for (int k = 0; k < n_in; k++) {
        int sz = in_sizes[k];
        if (sz == NN * NN)      adj   = (const float*)d_in[k];
        else if (sz == NN * DD) x     = (const float*)d_in[k];
        else if (sz == 2 * DD)  att_W = (const float*)d_in[k];
        else if (sz == 1)       att_b = (const float*)d_in[k];
    }
    float* out = (float*)d_out;

    hyp_all<<<NN, TPR>>>(x, adj, att_W, att_b, out);
}